// round 4
// baseline (speedup 1.0000x reference)
#include <cuda_runtime.h>

#define B_ 2
#define N_ 65536
#define C_ 256
#define H_ 8
#define D_ 64
#define S_ 64
#define TM 64
#define NCHUNK 64
#define TILES_PER_CTA ((N_ / TM) / NCHUNK)   // 16

// scratch (allowed: __device__ globals, no runtime allocation)
__device__ float g_A[B_ * H_ * S_ * D_];     // 65536 floats
__device__ float g_norm[B_ * H_ * S_];       // 1024 floats

typedef unsigned long long u64;

__device__ __forceinline__ u64 pk2(float x, float y) {
    u64 r; asm("mov.b64 %0,{%1,%2};" : "=l"(r) : "f"(x), "f"(y)); return r;
}
__device__ __forceinline__ float2 upk2(u64 v) {
    float2 r; asm("mov.b64 {%0,%1},%2;" : "=f"(r.x), "=f"(r.y) : "l"(v)); return r;
}
__device__ __forceinline__ u64 ffma2(u64 a, u64 b, u64 c) {
    u64 d; asm("fma.rn.f32x2 %0,%1,%2,%3;" : "=l"(d) : "l"(a), "l"(b), "l"(c)); return d;
}

// smem layout (floats)
#define SW_OFF   0          // 256*128 = 32768 : [k][128] cols 0..63 = W_x(head), 64..127 = W_fx(head)
#define SX_OFF   32768      // 64*68  : x chunk [token][kk], pitch 68
#define SSL_OFF  (SX_OFF + 64*68)   // 64*68 : W_slice [k][s], pitch 68
#define SP_OFF   (SSL_OFF + 64*68)  // 64*68 : p -> L -> w
#define SFX_OFF  (SP_OFF + 64*68)   // 64*68 : fx
#define SMEM_FLOATS (SFX_OFF + 64*68)       // 50176 floats = 200704 B

__global__ void k_zero() {
    int i = blockIdx.x * 256 + threadIdx.x;
    if (i < B_ * H_ * S_ * D_) g_A[i] = 0.0f;
    if (i < B_ * H_ * S_)      g_norm[i] = 0.0f;
}

__global__ __launch_bounds__(256, 1)
void k_fused(const float* __restrict__ x,
             const float* __restrict__ Wx,  const float* __restrict__ bx,
             const float* __restrict__ Wfx, const float* __restrict__ bfx,
             const float* __restrict__ Wsl, const float* __restrict__ bsl,
             const float* __restrict__ temp)
{
    extern __shared__ float sm[];
    float* sW  = sm + SW_OFF;
    float* sX  = sm + SX_OFF;
    float* sSl = sm + SSL_OFF;
    float* sP  = sm + SP_OFF;
    float* sFx = sm + SFX_OFF;

    const int tid  = threadIdx.x;
    const int b    = blockIdx.z, h = blockIdx.y;
    const int cg   = tid & 15;        // col group: 4 cols cg*4..+3 (both p and fx side)
    const int tg   = tid >> 4;        // token group: 4 tokens tg*4..+3  (also s-group in agg)
    const int lane = tid & 31, wid = tid >> 5;

    // ---- stage W (once per CTA): sW[k][0..63]=W_x cols of head, [64..127]=W_fx ----
    {
        const float4* Wx4  = (const float4*)Wx;
        const float4* Wfx4 = (const float4*)Wfx;
        float4* sW4 = (float4*)sW;
        #pragma unroll
        for (int j = 0; j < 32; j++) {
            int f4i = tid + j * 256;          // 0..8191
            int k = f4i >> 5, q = f4i & 31;   // 32 float4 per row
            float4 v = (q < 16) ? Wx4[k * 128 + h * 16 + q]
                                : Wfx4[k * 128 + h * 16 + (q - 16)];
            sW4[k * 32 + q] = v;
        }
    }
    // ---- stage W_slice [64][64] -> pitch 68 ----
    {
        const float4* Wsl4 = (const float4*)Wsl;
        #pragma unroll
        for (int j = 0; j < 4; j++) {
            int f4i = tid + j * 256;          // 0..1023
            int k = f4i >> 4, q = f4i & 15;
            *(float4*)&sSl[k * 68 + q * 4] = Wsl4[k * 16 + q];
        }
    }

    float tv = temp[h];
    tv = fminf(fmaxf(tv, 0.5f), 5.0f);
    const float invT = 1.0f / tv;
    const float4 bp = *(const float4*)(bx  + h * 64 + cg * 4);
    const float4 bf = *(const float4*)(bfx + h * 64 + cg * 4);
    const float4 bs = *(const float4*)(bsl + cg * 4);

    const float4* xg4 = (const float4*)x + (size_t)b * ((size_t)N_ * (C_ / 4));

    const u64* sWq  = (const u64*)sW;
    const u64* sSlq = (const u64*)sSl;
    const u64* sFxq = (const u64*)sFx;

    // persistent accumulators: A[s=tg*4+i][d=cg*4..+3], norm[s=tid] (tid<64)
    u64 accA[4][2];
    #pragma unroll
    for (int i = 0; i < 4; i++) { accA[i][0] = 0ull; accA[i][1] = 0ull; }
    float normAcc = 0.0f;

    for (int t = 0; t < TILES_PER_CTA; t++) {
        const int n0 = (blockIdx.x * TILES_PER_CTA + t) * TM;

        // ---- main GEMM: p,fx [64 tok x 128 cols], K=256 in 4 chunks ----
        u64 acc[4][4];
        #pragma unroll
        for (int i = 0; i < 4; i++)
            #pragma unroll
            for (int j = 0; j < 4; j++) acc[i][j] = 0ull;

        for (int kc = 0; kc < 4; kc++) {
            __syncthreads();
            // load x chunk: 64 tokens x 64 floats
            #pragma unroll
            for (int j = 0; j < 4; j++) {
                int f4i = tid + j * 256;       // 0..1023
                int tok = f4i >> 4, c4 = f4i & 15;
                float4 v = xg4[(size_t)(n0 + tok) * 64 + kc * 16 + c4];
                *(float4*)&sX[tok * 68 + c4 * 4] = v;
            }
            __syncthreads();

            #pragma unroll 8
            for (int kk = 0; kk < 64; kk++) {
                const int k = kc * 64 + kk;
                u64 bp0 = sWq[k * 64 + cg * 2];
                u64 bp1 = sWq[k * 64 + cg * 2 + 1];
                u64 bf0 = sWq[k * 64 + 32 + cg * 2];
                u64 bf1 = sWq[k * 64 + 32 + cg * 2 + 1];
                #pragma unroll
                for (int i = 0; i < 4; i++) {
                    float a = sX[(tg * 4 + i) * 68 + kk];
                    u64 a2 = pk2(a, a);
                    acc[i][0] = ffma2(a2, bp0, acc[i][0]);
                    acc[i][1] = ffma2(a2, bp1, acc[i][1]);
                    acc[i][2] = ffma2(a2, bf0, acc[i][2]);
                    acc[i][3] = ffma2(a2, bf1, acc[i][3]);
                }
            }
        }

        // ---- bias + stage p/fx ----
        #pragma unroll
        for (int i = 0; i < 4; i++) {
            float2 p01 = upk2(acc[i][0]), p23 = upk2(acc[i][1]);
            float2 f01 = upk2(acc[i][2]), f23 = upk2(acc[i][3]);
            int tok = tg * 4 + i;
            *(float4*)&sP[tok * 68 + cg * 4] =
                make_float4(p01.x + bp.x, p01.y + bp.y, p23.x + bp.z, p23.y + bp.w);
            *(float4*)&sFx[tok * 68 + cg * 4] =
                make_float4(f01.x + bf.x, f01.y + bf.y, f23.x + bf.z, f23.y + bf.w);
        }
        __syncthreads();

        // ---- slice GEMM: L[64 tok x 64 s] = p @ Wsl ----
        u64 accL[4][2];
        #pragma unroll
        for (int i = 0; i < 4; i++) { accL[i][0] = 0ull; accL[i][1] = 0ull; }
        #pragma unroll 8
        for (int k = 0; k < 64; k++) {
            u64 b0 = sSlq[k * 34 + cg * 2];
            u64 b1 = sSlq[k * 34 + cg * 2 + 1];
            #pragma unroll
            for (int i = 0; i < 4; i++) {
                float a = sP[(tg * 4 + i) * 68 + k];
                u64 a2 = pk2(a, a);
                accL[i][0] = ffma2(a2, b0, accL[i][0]);
                accL[i][1] = ffma2(a2, b1, accL[i][1]);
            }
        }
        __syncthreads();   // all reads of p done; reuse sP for logits
        #pragma unroll
        for (int i = 0; i < 4; i++) {
            float2 l01 = upk2(accL[i][0]), l23 = upk2(accL[i][1]);
            int tok = tg * 4 + i;
            *(float4*)&sP[tok * 68 + cg * 4] =
                make_float4((l01.x + bs.x) * invT, (l01.y + bs.y) * invT,
                            (l23.x + bs.z) * invT, (l23.y + bs.w) * invT);
        }
        __syncthreads();

        // ---- softmax over S=64, 8 tokens per warp ----
        #pragma unroll
        for (int tt = 0; tt < 8; tt++) {
            int tok = wid * 8 + tt;
            float v0 = sP[tok * 68 + lane];
            float v1 = sP[tok * 68 + 32 + lane];
            float m = fmaxf(v0, v1);
            #pragma unroll
            for (int o = 16; o > 0; o >>= 1) m = fmaxf(m, __shfl_xor_sync(0xffffffffu, m, o));
            float e0 = __expf(v0 - m), e1 = __expf(v1 - m);
            float s = e0 + e1;
            #pragma unroll
            for (int o = 16; o > 0; o >>= 1) s += __shfl_xor_sync(0xffffffffu, s, o);
            float r = __frcp_rn(s);
            sP[tok * 68 + lane]      = e0 * r;
            sP[tok * 68 + 32 + lane] = e1 * r;
        }
        __syncthreads();

        // ---- per-tile column sum of w into persistent register ----
        if (tid < 64) {
            float sw = 0.0f;
            #pragma unroll 8
            for (int n = 0; n < 64; n++) sw += sP[n * 68 + tid];
            normAcc += sw;
        }

        // ---- aggregation: A[s][d] += sum_n w[n][s] * fx[n][d] ----
        #pragma unroll 4
        for (int n = 0; n < 64; n++) {
            u64 fx0 = sFxq[n * 34 + cg * 2];
            u64 fx1 = sFxq[n * 34 + cg * 2 + 1];
            #pragma unroll
            for (int i = 0; i < 4; i++) {
                float w = sP[n * 68 + tg * 4 + i];
                u64 w2 = pk2(w, w);
                accA[i][0] = ffma2(w2, fx0, accA[i][0]);
                accA[i][1] = ffma2(w2, fx1, accA[i][1]);
            }
        }
        // next tile's first __syncthreads() protects sX/sP/sFx reuse
    }

    // ---- flush partials ----
    float* gA = g_A + ((size_t)(b * H_ + h) * S_) * D_;
    #pragma unroll
    for (int i = 0; i < 4; i++) {
        float2 v0 = upk2(accA[i][0]), v1 = upk2(accA[i][1]);
        int s = tg * 4 + i;
        atomicAdd(&gA[s * D_ + cg * 4 + 0], v0.x);
        atomicAdd(&gA[s * D_ + cg * 4 + 1], v0.y);
        atomicAdd(&gA[s * D_ + cg * 4 + 2], v1.x);
        atomicAdd(&gA[s * D_ + cg * 4 + 3], v1.y);
    }
    if (tid < 64) atomicAdd(&g_norm[(b * H_ + h) * S_ + tid], normAcc);
}

__global__ void k_final(float* __restrict__ out) {
    int i = blockIdx.x * 256 + threadIdx.x;   // < 65536
    out[i] = g_A[i] / (g_norm[i >> 6] + 0.01f);
}

extern "C" void kernel_launch(void* const* d_in, const int* in_sizes, int n_in,
                              void* d_out, int out_size) {
    const float* x    = (const float*)d_in[0];
    const float* Wx   = (const float*)d_in[1];
    const float* bx   = (const float*)d_in[2];
    const float* Wfx  = (const float*)d_in[3];
    const float* bfx  = (const float*)d_in[4];
    const float* Wsl  = (const float*)d_in[5];
    const float* bsl  = (const float*)d_in[6];
    const float* temp = (const float*)d_in[7];
    float* out = (float*)d_out;

    const int smem_bytes = SMEM_FLOATS * 4;   // 200704 B
    cudaFuncSetAttribute(k_fused, cudaFuncAttributeMaxDynamicSharedMemorySize, smem_bytes);

    k_zero<<<256, 256>>>();
    dim3 grid(NCHUNK, H_, B_);
    k_fused<<<grid, 256, smem_bytes>>>(x, Wx, bx, Wfx, bfx, Wsl, bsl, temp);
    k_final<<<256, 256>>>(out);
}

// round 5
// speedup vs baseline: 2.4925x; 2.4925x over previous
#include <cuda_runtime.h>

#define B_ 2
#define N_ 65536
#define C_ 256
#define H_ 8
#define D_ 64
#define S_ 64
#define TM 128
#define NCHUNK 64
#define TILES_PER_CTA ((N_ / TM) / NCHUNK)   // 8

// scratch
__device__ float g_A[B_ * H_ * S_ * D_];
__device__ float g_norm[B_ * H_ * S_];

// smem layout (floats)
#define PW  264
#define PX  72
#define SW_OFF  0
#define SX_OFF  (128 * PW)                 // 33792
#define SFX_OFF (SX_OFF + 128 * PX)        // 43008
#define SSL_OFF (SFX_OFF + 128 * PX)       // 52224
#define SMEM_FLOATS (SSL_OFF + 64 * PX)    // 56832 -> 227328 B

__device__ __forceinline__ unsigned f2tf(float x) {
    unsigned r; asm("cvt.rna.tf32.f32 %0, %1;" : "=r"(r) : "f"(x)); return r;
}
__device__ __forceinline__ float tfF(float x) { return __uint_as_float(f2tf(x)); }

__device__ __forceinline__ void mma8(float* d, unsigned a0, unsigned a1, unsigned a2,
                                     unsigned a3, unsigned b0, unsigned b1) {
    asm volatile("mma.sync.aligned.m16n8k8.row.col.f32.tf32.tf32.f32 "
                 "{%0,%1,%2,%3},{%4,%5,%6,%7},{%8,%9},{%0,%1,%2,%3};"
                 : "+f"(d[0]), "+f"(d[1]), "+f"(d[2]), "+f"(d[3])
                 : "r"(a0), "r"(a1), "r"(a2), "r"(a3), "r"(b0), "r"(b1));
}
__device__ __forceinline__ int jmap(int j) { return 2 * (j & 3) + (j >> 2); }

__global__ void k_zero() {
    int i = blockIdx.x * 256 + threadIdx.x;
    if (i < B_ * H_ * S_ * D_) g_A[i] = 0.0f;
    if (i < B_ * H_ * S_)      g_norm[i] = 0.0f;
}

__global__ __launch_bounds__(256, 1)
void k_fused(const float* __restrict__ x,
             const float* __restrict__ Wx,  const float* __restrict__ bx,
             const float* __restrict__ Wfx, const float* __restrict__ bfx,
             const float* __restrict__ Wsl, const float* __restrict__ bsl,
             const float* __restrict__ temp)
{
    extern __shared__ float sm[];
    float* sW   = sm + SW_OFF;
    float* sX   = sm + SX_OFF;     // aliased as sP (p, d-interleaved) and sWgt (w)
    float* sFx  = sm + SFX_OFF;
    float* sSl  = sm + SSL_OFF;
    float* sP   = sX;
    float* sWgt = sX;

    const int tid  = threadIdx.x;
    const int b    = blockIdx.z, h = blockIdx.y;
    const int lane = tid & 31, wp = tid >> 5;
    const int g    = lane >> 2, t = lane & 3;

    // main-gemm warp tiling: 4 m-warps x 2 n-warps
    const int mw = wp >> 1, nw = wp & 1;
    const int tokBase = mw * 32;
    const int colBase = nw * 64;
    // agg warp tiling: 4 m-warps (s) x 2 n-warps (d)
    const int sBase = (wp >> 1) * 16;
    const int dBase = (wp & 1) * 32;

    // ---- stage W (once): sW[n 0..127][kIL(k)], tf32 ----
    {
        const float4* Wx4  = (const float4*)Wx;
        const float4* Wfx4 = (const float4*)Wfx;
        #pragma unroll
        for (int jj = 0; jj < 32; jj++) {
            int f = tid + jj * 256;          // 0..8191
            int k = f >> 5, q = f & 31;
            float4 v = (q < 16) ? Wx4[k * 128 + h * 16 + q]
                                : Wfx4[k * 128 + h * 16 + (q - 16)];
            int scol = 8 * (k >> 3) + jmap(k & 7);
            int nl = 4 * q;                  // nlocal base (p: q<16 -> 0..63, fx: 64..127)
            sW[(nl + 0) * PW + scol] = tfF(v.x);
            sW[(nl + 1) * PW + scol] = tfF(v.y);
            sW[(nl + 2) * PW + scol] = tfF(v.z);
            sW[(nl + 3) * PW + scol] = tfF(v.w);
        }
        const float4* Wsl4 = (const float4*)Wsl;
        #pragma unroll
        for (int jj = 0; jj < 4; jj++) {
            int f = tid + jj * 256;          // 0..1023
            int d = f >> 4, q = f & 15;
            float4 v = Wsl4[d * 16 + q];
            sSl[d * PX + 4 * q + 0] = tfF(v.x);
            sSl[d * PX + 4 * q + 1] = tfF(v.y);
            sSl[d * PX + 4 * q + 2] = tfF(v.z);
            sSl[d * PX + 4 * q + 3] = tfF(v.w);
        }
    }

    float tv = fminf(fmaxf(temp[h], 0.5f), 5.0f);
    const float invT = 1.0f / tv;

    // per-thread bias fragments: col d = 8j + 2t + e
    float bPF[16], bS[16];
    const float* bpf = nw ? (bfx + h * 64) : (bx + h * 64);
    #pragma unroll
    for (int j = 0; j < 8; j++)
        #pragma unroll
        for (int e = 0; e < 2; e++) {
            int d = 8 * j + 2 * t + e;
            bPF[2 * j + e] = bpf[d];
            bS[2 * j + e]  = bsl[d];
        }
    const int sc0 = jmap(2 * t), sc1 = jmap(2 * t + 1);

    // persistent accumulators
    float aggAcc[4][4];
    #pragma unroll
    for (int j = 0; j < 4; j++)
        #pragma unroll
        for (int e = 0; e < 4; e++) aggAcc[j][e] = 0.0f;
    float normAcc[16];
    #pragma unroll
    for (int i = 0; i < 16; i++) normAcc[i] = 0.0f;

    const float4* xg4 = (const float4*)x + (size_t)b * (size_t)N_ * 64;

    for (int tnum = 0; tnum < TILES_PER_CTA; tnum++) {
        const int n0 = (blockIdx.x * TILES_PER_CTA + tnum) * TM;

        // ---- main GEMM: [128 tok x 128 col], K=256 ----
        float acc[2][8][4];
        #pragma unroll
        for (int i = 0; i < 2; i++)
            #pragma unroll
            for (int j = 0; j < 8; j++)
                #pragma unroll
                for (int e = 0; e < 4; e++) acc[i][j][e] = 0.0f;

        for (int kc = 0; kc < 4; kc++) {
            __syncthreads();
            // load x chunk (tf32, k-interleaved): 128 tok x 64
            #pragma unroll
            for (int jj = 0; jj < 8; jj++) {
                int f = tid + jj * 256;       // 0..2047
                int tok = f >> 4, c4 = f & 15;
                float4 v = xg4[(size_t)(n0 + tok) * 64 + kc * 16 + c4];
                int sb = tok * PX + 8 * (c4 >> 1) + (c4 & 1);
                sX[sb + 0] = tfF(v.x);
                sX[sb + 2] = tfF(v.y);
                sX[sb + 4] = tfF(v.z);
                sX[sb + 6] = tfF(v.w);
            }
            __syncthreads();

            #pragma unroll
            for (int ks = 0; ks < 8; ks++) {
                const int kg = kc * 8 + ks;
                unsigned a[2][4];
                #pragma unroll
                for (int i = 0; i < 2; i++) {
                    uint2 lo = *(const uint2*)&sX[(tokBase + 16 * i + g) * PX + 8 * ks + 2 * t];
                    uint2 hi = *(const uint2*)&sX[(tokBase + 16 * i + g + 8) * PX + 8 * ks + 2 * t];
                    a[i][0] = lo.x; a[i][2] = lo.y; a[i][1] = hi.x; a[i][3] = hi.y;
                }
                #pragma unroll
                for (int j = 0; j < 8; j++) {
                    uint2 bb = *(const uint2*)&sW[(colBase + 8 * j + g) * PW + 8 * kg + 2 * t];
                    mma8(acc[0][j], a[0][0], a[0][1], a[0][2], a[0][3], bb.x, bb.y);
                    mma8(acc[1][j], a[1][0], a[1][1], a[1][2], a[1][3], bb.x, bb.y);
                }
            }
        }

        __syncthreads();   // all sX reads done before sP overwrite

        if (nw == 0) {
            // p: +bias, tf32, d-interleaved cols into sP
            #pragma unroll
            for (int i = 0; i < 2; i++)
                #pragma unroll
                for (int j = 0; j < 8; j++) {
                    int r0 = tokBase + 16 * i + g;
                    sP[r0 * PX + 8 * j + sc0]       = tfF(acc[i][j][0] + bPF[2 * j + 0]);
                    sP[r0 * PX + 8 * j + sc1]       = tfF(acc[i][j][1] + bPF[2 * j + 1]);
                    sP[(r0 + 8) * PX + 8 * j + sc0] = tfF(acc[i][j][2] + bPF[2 * j + 0]);
                    sP[(r0 + 8) * PX + 8 * j + sc1] = tfF(acc[i][j][3] + bPF[2 * j + 1]);
                }
        } else {
            // fx: +bias, tf32, plain cols into sFx
            #pragma unroll
            for (int i = 0; i < 2; i++)
                #pragma unroll
                for (int j = 0; j < 8; j++) {
                    int r0 = tokBase + 16 * i + g;
                    int c  = 8 * j + 2 * t;
                    sFx[r0 * PX + c]           = tfF(acc[i][j][0] + bPF[2 * j + 0]);
                    sFx[r0 * PX + c + 1]       = tfF(acc[i][j][1] + bPF[2 * j + 1]);
                    sFx[(r0 + 8) * PX + c]     = tfF(acc[i][j][2] + bPF[2 * j + 0]);
                    sFx[(r0 + 8) * PX + c + 1] = tfF(acc[i][j][3] + bPF[2 * j + 1]);
                }
        }
        __syncthreads();

        // ---- slice GEMM: L[128 tok x 64 s] = p @ Wsl; warp owns 16 tokens x 64 s ----
        float accS[8][4];
        #pragma unroll
        for (int j = 0; j < 8; j++)
            #pragma unroll
            for (int e = 0; e < 4; e++) accS[j][e] = 0.0f;
        #pragma unroll
        for (int ks = 0; ks < 8; ks++) {
            uint2 lo = *(const uint2*)&sP[(16 * wp + g) * PX + 8 * ks + 2 * t];
            uint2 hi = *(const uint2*)&sP[(16 * wp + g + 8) * PX + 8 * ks + 2 * t];
            #pragma unroll
            for (int j = 0; j < 8; j++) {
                unsigned b0 = __float_as_uint(sSl[(8 * ks + t) * PX + 8 * j + g]);
                unsigned b1 = __float_as_uint(sSl[(8 * ks + t + 4) * PX + 8 * j + g]);
                mma8(accS[j], lo.x, hi.x, lo.y, hi.y, b0, b1);
            }
        }

        // ---- softmax (registers + quad shuffles); rows r0=16wp+g, r1=r0+8 ----
        float w0[16], w1[16];
        #pragma unroll
        for (int j = 0; j < 8; j++)
            #pragma unroll
            for (int e = 0; e < 2; e++) {
                w0[2 * j + e] = (accS[j][e]     + bS[2 * j + e]) * invT;
                w1[2 * j + e] = (accS[j][2 + e] + bS[2 * j + e]) * invT;
            }
        float m0 = w0[0], m1 = w1[0];
        #pragma unroll
        for (int i = 1; i < 16; i++) { m0 = fmaxf(m0, w0[i]); m1 = fmaxf(m1, w1[i]); }
        m0 = fmaxf(m0, __shfl_xor_sync(0xffffffffu, m0, 1));
        m0 = fmaxf(m0, __shfl_xor_sync(0xffffffffu, m0, 2));
        m1 = fmaxf(m1, __shfl_xor_sync(0xffffffffu, m1, 1));
        m1 = fmaxf(m1, __shfl_xor_sync(0xffffffffu, m1, 2));
        float s0 = 0.0f, s1 = 0.0f;
        #pragma unroll
        for (int i = 0; i < 16; i++) {
            w0[i] = __expf(w0[i] - m0); s0 += w0[i];
            w1[i] = __expf(w1[i] - m1); s1 += w1[i];
        }
        s0 += __shfl_xor_sync(0xffffffffu, s0, 1);
        s0 += __shfl_xor_sync(0xffffffffu, s0, 2);
        s1 += __shfl_xor_sync(0xffffffffu, s1, 1);
        s1 += __shfl_xor_sync(0xffffffffu, s1, 2);
        float r0inv = __frcp_rn(s0), r1inv = __frcp_rn(s1);

        // write w (tf32) into sWgt[tok][s]; accumulate norm from the same tf32 values
        {
            int rr = 16 * wp + g;
            #pragma unroll
            for (int j = 0; j < 8; j++) {
                float a0 = tfF(w0[2 * j + 0] * r0inv);
                float a1 = tfF(w0[2 * j + 1] * r0inv);
                float c0 = tfF(w1[2 * j + 0] * r1inv);
                float c1 = tfF(w1[2 * j + 1] * r1inv);
                *(float2*)&sWgt[rr * PX + 8 * j + 2 * t]       = make_float2(a0, a1);
                *(float2*)&sWgt[(rr + 8) * PX + 8 * j + 2 * t] = make_float2(c0, c1);
                normAcc[2 * j + 0] += a0 + c0;
                normAcc[2 * j + 1] += a1 + c1;
            }
        }
        __syncthreads();

        // ---- aggregation: A[s,d] += w^T @ fx ; K = 128 tokens ----
        #pragma unroll
        for (int ks = 0; ks < 16; ks++) {
            unsigned a0 = __float_as_uint(sWgt[(8 * ks + t) * PX + sBase + g]);
            unsigned a1 = __float_as_uint(sWgt[(8 * ks + t) * PX + sBase + g + 8]);
            unsigned a2 = __float_as_uint(sWgt[(8 * ks + t + 4) * PX + sBase + g]);
            unsigned a3 = __float_as_uint(sWgt[(8 * ks + t + 4) * PX + sBase + g + 8]);
            #pragma unroll
            for (int j = 0; j < 4; j++) {
                unsigned b0 = __float_as_uint(sFx[(8 * ks + t) * PX + dBase + 8 * j + g]);
                unsigned b1 = __float_as_uint(sFx[(8 * ks + t + 4) * PX + dBase + 8 * j + g]);
                mma8(aggAcc[j], a0, a1, a2, a3, b0, b1);
            }
        }
        // next tile's first __syncthreads() protects sX/sWgt/sFx reuse
    }

    // ---- flush ----
    float* gA = g_A + (size_t)((b * H_ + h) * S_) * D_;
    #pragma unroll
    for (int j = 0; j < 4; j++) {
        int d0 = dBase + 8 * j + 2 * t;
        atomicAdd(&gA[(sBase + g) * 64 + d0],         aggAcc[j][0]);
        atomicAdd(&gA[(sBase + g) * 64 + d0 + 1],     aggAcc[j][1]);
        atomicAdd(&gA[(sBase + g + 8) * 64 + d0],     aggAcc[j][2]);
        atomicAdd(&gA[(sBase + g + 8) * 64 + d0 + 1], aggAcc[j][3]);
    }
    #pragma unroll
    for (int i = 0; i < 16; i++) {
        float v = normAcc[i];
        v += __shfl_xor_sync(0xffffffffu, v, 4);
        v += __shfl_xor_sync(0xffffffffu, v, 8);
        v += __shfl_xor_sync(0xffffffffu, v, 16);
        if (g == 0)
            atomicAdd(&g_norm[(b * H_ + h) * S_ + 8 * (i >> 1) + 2 * t + (i & 1)], v);
    }
}

__global__ void k_final(float* __restrict__ out) {
    int i = blockIdx.x * 256 + threadIdx.x;
    out[i] = g_A[i] / (g_norm[i >> 6] + 0.01f);
}

extern "C" void kernel_launch(void* const* d_in, const int* in_sizes, int n_in,
                              void* d_out, int out_size) {
    const float* x    = (const float*)d_in[0];
    const float* Wx   = (const float*)d_in[1];
    const float* bx   = (const float*)d_in[2];
    const float* Wfx  = (const float*)d_in[3];
    const float* bfx  = (const float*)d_in[4];
    const float* Wsl  = (const float*)d_in[5];
    const float* bsl  = (const float*)d_in[6];
    const float* temp = (const float*)d_in[7];
    float* out = (float*)d_out;

    const int smem_bytes = SMEM_FLOATS * 4;   // 227328 B
    cudaFuncSetAttribute(k_fused, cudaFuncAttributeMaxDynamicSharedMemorySize, smem_bytes);

    k_zero<<<256, 256>>>();
    dim3 grid(NCHUNK, H_, B_);
    k_fused<<<grid, 256, smem_bytes>>>(x, Wx, bx, Wfx, bfx, Wsl, bsl, temp);
    k_final<<<256, 256>>>(out);
}

// round 7
// speedup vs baseline: 3.2509x; 1.3042x over previous
#include <cuda_runtime.h>
#include <cstdint>

#define B_ 2
#define N_ 65536
#define H_ 8
#define TILES_PER_CTA 8
#define NCHUNK 64

// ---- smem layout (float offsets) ----
#define PW    260
#define SW_F  0                    // W [n 0..127][k 0..255] pitch 260 (p cols 0-63, fx 64-127)
#define SX_F  33280                // 2 x (128 tok x 36 pitch) chunk bufs ; aliased by sFxT
#define PXC   36
#define BUFB  (128 * PXC * 4)      // 18432 B per buf
#define PT    132                  // transposed fx / w pitch
#define SP_F  42496                // p [tok][d] pitch 68 ; aliased by sWgtT [s][tok] pitch 132
#define PP    68
#define SSL_F 51200                // Wsl [s][d] pitch 68
#define SRED_F 55552               // softmax exchange: max [0..255], sum [256..511]
#define SBIAS_F 56064              // 128 floats
#define SMEM_FLOATS 56192          // 224768 B

__device__ float g_A[B_ * H_ * 64 * 64];
__device__ float g_norm[B_ * H_ * 64];

__device__ __forceinline__ uint32_t smem_u32(const void* p) {
    uint32_t a;
    asm("{ .reg .u64 t; cvta.to.shared.u64 t, %1; cvt.u32.u64 %0, t; }" : "=r"(a) : "l"(p));
    return a;
}
__device__ __forceinline__ unsigned f2tf(float x) {
    unsigned r; asm("cvt.rna.tf32.f32 %0, %1;" : "=r"(r) : "f"(x)); return r;
}
__device__ __forceinline__ float tfF(float x) { return __uint_as_float(f2tf(x)); }

__device__ __forceinline__ void mma8(float* d, unsigned a0, unsigned a1, unsigned a2,
                                     unsigned a3, unsigned b0, unsigned b1) {
    asm volatile("mma.sync.aligned.m16n8k8.row.col.f32.tf32.tf32.f32 "
                 "{%0,%1,%2,%3},{%4,%5,%6,%7},{%8,%9},{%0,%1,%2,%3};"
                 : "+f"(d[0]), "+f"(d[1]), "+f"(d[2]), "+f"(d[3])
                 : "r"(a0), "r"(a1), "r"(a2), "r"(a3), "r"(b0), "r"(b1));
}
__device__ __forceinline__ void ldsm4(uint32_t addr, unsigned& r0, unsigned& r1,
                                      unsigned& r2, unsigned& r3) {
    asm volatile("ldmatrix.sync.aligned.m8n8.x4.shared.b16 {%0,%1,%2,%3}, [%4];"
                 : "=r"(r0), "=r"(r1), "=r"(r2), "=r"(r3) : "r"(addr));
}
__device__ __forceinline__ void cpa16(uint32_t dst, const void* src) {
    asm volatile("cp.async.cg.shared.global [%0], [%1], 16;" :: "r"(dst), "l"(src));
}
#define CPA_COMMIT() asm volatile("cp.async.commit_group;" ::: "memory")
#define CPA_WAIT1()  asm volatile("cp.async.wait_group 1;" ::: "memory")
#define CPA_WAIT0()  asm volatile("cp.async.wait_group 0;" ::: "memory")

__global__ void k_zero() {
    int i = blockIdx.x * 256 + threadIdx.x;
    if (i < B_ * H_ * 64 * 64) g_A[i] = 0.0f;
    if (i < B_ * H_ * 64)      g_norm[i] = 0.0f;
}

__global__ __launch_bounds__(512, 1)
void k_fused(const float* __restrict__ x,
             const float* __restrict__ Wx,  const float* __restrict__ bx,
             const float* __restrict__ Wfx, const float* __restrict__ bfx,
             const float* __restrict__ Wsl, const float* __restrict__ bsl,
             const float* __restrict__ temp)
{
    extern __shared__ float sm[];
    float* sW    = sm + SW_F;
    float* sP    = sm + SP_F;
    float* sWgtT = sm + SP_F;      // alias
    float* sFxT  = sm + SX_F;      // alias
    float* sSl   = sm + SSL_F;
    float* sRedM = sm + SRED_F;
    float* sRedS = sm + SRED_F + 256;
    float* sBias = sm + SBIAS_F;

    const uint32_t sb  = smem_u32(sm);
    const uint32_t sXu = sb + SX_F * 4;
    const uint32_t sWu = sb + SW_F * 4;
    const uint32_t sPu = sb + SP_F * 4;
    const uint32_t sSlu = sb + SSL_F * 4;
    const uint32_t sWgtu = sPu;
    const uint32_t sFxu  = sXu;

    const int tid  = threadIdx.x;
    const int b    = blockIdx.z, h = blockIdx.y;
    const int lane = tid & 31, wid = tid >> 5;
    const int g    = lane >> 2, t = lane & 3;

    // main GEMM roles: 4 m-warps x 4 n-warps
    const int tokBase = (wid >> 2) * 32;
    const int nw      = wid & 3;
    const int colBase = nw * 32;
    // slice roles: 8 m-warps x 2 n-warps
    const int smw = wid >> 1, snw = wid & 1;
    const int tokB2 = smw * 16, sB2 = snw * 32;
    // agg roles: 4 (s) x 4 (d)
    const int sB3 = (wid >> 2) * 16, dB3 = (wid & 3) * 16;

    // ---- stage W [n][k] plain, tf32 ----
    {
        const float4* Wx4  = (const float4*)Wx;
        const float4* Wfx4 = (const float4*)Wfx;
        #pragma unroll
        for (int it = 0; it < 16; it++) {
            int f = tid + it * 512;            // 0..8191
            int k = f >> 5, q = f & 31;
            float4 v = (q < 16) ? Wx4[k * 128 + h * 16 + q]
                                : Wfx4[k * 128 + h * 16 + (q - 16)];
            int n = 4 * q;
            sW[(n + 0) * PW + k] = tfF(v.x);
            sW[(n + 1) * PW + k] = tfF(v.y);
            sW[(n + 2) * PW + k] = tfF(v.z);
            sW[(n + 3) * PW + k] = tfF(v.w);
        }
        #pragma unroll
        for (int it = 0; it < 8; it++) {
            int f = tid + it * 512;            // 0..4095
            int d = f >> 6, s = f & 63;
            sSl[s * PP + d] = tfF(Wsl[f]);
        }
        if (tid < 128)
            sBias[tid] = (tid < 64) ? bx[h * 64 + tid] : bfx[h * 64 + (tid - 64)];
    }
    __syncthreads();

    float tv = fminf(fmaxf(temp[h], 0.5f), 5.0f);
    const float invT = 1.0f / tv;
    float bS[8];
    #pragma unroll
    for (int j = 0; j < 4; j++)
        #pragma unroll
        for (int e = 0; e < 2; e++) bS[2 * j + e] = bsl[sB2 + 8 * j + 2 * t + e];

    // ldmatrix per-thread bases
    const int rA = (lane & 7) + 8 * ((lane >> 3) & 1);
    const int cA = (lane >> 4) & 1;
    const uint32_t aA0 = sXu + (uint32_t)(tokBase + rA) * (PXC * 4) + cA * 16;
    const int rB = (lane & 7) + 8 * ((lane >> 4) & 1);
    const int cB = (lane >> 3) & 1;
    const uint32_t bB0 = sWu + (uint32_t)(colBase + rB) * (PW * 4) + cB * 16;
    const uint32_t pA0 = sPu + (uint32_t)(tokB2 + rA) * (PP * 4) + cA * 16;
    const uint32_t slB0 = sSlu + (uint32_t)(sB2 + rB) * (PP * 4) + cB * 16;
    const uint32_t wA0 = sWgtu + (uint32_t)(sB3 + rA) * (PT * 4) + cA * 16;
    const uint32_t fB0 = sFxu + (uint32_t)(dB3 + rB) * (PT * 4) + cB * 16;

    float aggAcc[2][4];
    #pragma unroll
    for (int j = 0; j < 2; j++)
        #pragma unroll
        for (int e = 0; e < 4; e++) aggAcc[j][e] = 0.0f;
    float na[8];
    #pragma unroll
    for (int i = 0; i < 8; i++) na[i] = 0.0f;

    const float4* xg4 = (const float4*)x + (size_t)b * (size_t)N_ * 64;
    const int cTok = tid >> 2, cQ = 2 * (tid & 3);

    for (int tnum = 0; tnum < TILES_PER_CTA; tnum++) {
        const int n0 = (blockIdx.x * TILES_PER_CTA + tnum) * 128;
        __syncthreads();   // U1/U2 free from previous tile's reads

        float acc[2][4][4];
        #pragma unroll
        for (int i = 0; i < 2; i++)
            #pragma unroll
            for (int j = 0; j < 4; j++)
                #pragma unroll
                for (int e = 0; e < 4; e++) acc[i][j][e] = 0.0f;

        // prologue: chunks 0,1
        #pragma unroll
        for (int c = 0; c < 2; c++) {
            const float4* src = xg4 + (size_t)(n0 + cTok) * 64 + c * 8 + cQ;
            uint32_t dst = sXu + c * BUFB + cTok * (PXC * 4) + cQ * 16;
            cpa16(dst, src); cpa16(dst + 16, src + 1);
            CPA_COMMIT();
        }

        for (int c = 0; c < 8; c++) {
            const int bb = c & 1;
            if (c < 7) CPA_WAIT1(); else CPA_WAIT0();
            __syncthreads();

            const uint32_t aB = aA0 + bb * BUFB;
            const uint32_t kB = bB0 + (uint32_t)c * 128;
            #pragma unroll
            for (int ksl = 0; ksl < 4; ksl++) {
                unsigned a0[4], a1[4], p0, p1, p2, p3;
                ldsm4(aB + ksl * 32, a0[0], a0[1], a0[2], a0[3]);
                ldsm4(aB + 16 * (PXC * 4) + ksl * 32, a1[0], a1[1], a1[2], a1[3]);
                ldsm4(kB + ksl * 32, p0, p1, p2, p3);
                mma8(acc[0][0], a0[0], a0[1], a0[2], a0[3], p0, p1);
                mma8(acc[0][1], a0[0], a0[1], a0[2], a0[3], p2, p3);
                mma8(acc[1][0], a1[0], a1[1], a1[2], a1[3], p0, p1);
                mma8(acc[1][1], a1[0], a1[1], a1[2], a1[3], p2, p3);
                ldsm4(kB + 16 * (PW * 4) + ksl * 32, p0, p1, p2, p3);
                mma8(acc[0][2], a0[0], a0[1], a0[2], a0[3], p0, p1);
                mma8(acc[0][3], a0[0], a0[1], a0[2], a0[3], p2, p3);
                mma8(acc[1][2], a1[0], a1[1], a1[2], a1[3], p0, p1);
                mma8(acc[1][3], a1[0], a1[1], a1[2], a1[3], p2, p3);
            }
            __syncthreads();
            if (c < 6) {
                const int cn = c + 2;
                const float4* src = xg4 + (size_t)(n0 + cTok) * 64 + cn * 8 + cQ;
                uint32_t dst = sXu + bb * BUFB + cTok * (PXC * 4) + cQ * 16;
                cpa16(dst, src); cpa16(dst + 16, src + 1);
                CPA_COMMIT();
            }
        }

        // ---- p / fx stores ----
        if (nw < 2) {
            #pragma unroll
            for (int i = 0; i < 2; i++)
                #pragma unroll
                for (int j = 0; j < 4; j++) {
                    int row = tokBase + 16 * i + g;
                    int col = colBase + 8 * j + 2 * t;
                    *(float2*)&sP[row * PP + col] = make_float2(
                        tfF(acc[i][j][0] + sBias[col]), tfF(acc[i][j][1] + sBias[col + 1]));
                    *(float2*)&sP[(row + 8) * PP + col] = make_float2(
                        tfF(acc[i][j][2] + sBias[col]), tfF(acc[i][j][3] + sBias[col + 1]));
                }
        } else {
            #pragma unroll
            for (int i = 0; i < 2; i++)
                #pragma unroll
                for (int j = 0; j < 4; j++) {
                    int row = tokBase + 16 * i + g;
                    #pragma unroll
                    for (int e = 0; e < 2; e++) {
                        int d = (colBase - 64) + 8 * j + 2 * t + e;
                        sFxT[d * PT + row]     = tfF(acc[i][j][e]     + sBias[64 + d]);
                        sFxT[d * PT + row + 8] = tfF(acc[i][j][2 + e] + sBias[64 + d]);
                    }
                }
        }
        __syncthreads();

        // ---- slice GEMM: warp = 16 tokens x 32 s ----
        float accS[4][4];
        #pragma unroll
        for (int j = 0; j < 4; j++)
            #pragma unroll
            for (int e = 0; e < 4; e++) accS[j][e] = 0.0f;
        #pragma unroll
        for (int ks = 0; ks < 8; ks++) {
            unsigned a0, a1, a2, a3, p0, p1, p2, p3;
            ldsm4(pA0 + ks * 32, a0, a1, a2, a3);
            ldsm4(slB0 + ks * 32, p0, p1, p2, p3);
            mma8(accS[0], a0, a1, a2, a3, p0, p1);
            mma8(accS[1], a0, a1, a2, a3, p2, p3);
            ldsm4(slB0 + 16 * (PP * 4) + ks * 32, p0, p1, p2, p3);
            mma8(accS[2], a0, a1, a2, a3, p0, p1);
            mma8(accS[3], a0, a1, a2, a3, p2, p3);
        }

        // ---- softmax: 64 s split across snw pair, smem exchange ----
        float w0[8], w1[8];
        #pragma unroll
        for (int j = 0; j < 4; j++)
            #pragma unroll
            for (int e = 0; e < 2; e++) {
                w0[2 * j + e] = (accS[j][e]     + bS[2 * j + e]) * invT;
                w1[2 * j + e] = (accS[j][2 + e] + bS[2 * j + e]) * invT;
            }
        float m0 = w0[0], m1 = w1[0];
        #pragma unroll
        for (int i = 1; i < 8; i++) { m0 = fmaxf(m0, w0[i]); m1 = fmaxf(m1, w1[i]); }
        m0 = fmaxf(m0, __shfl_xor_sync(0xffffffffu, m0, 1));
        m0 = fmaxf(m0, __shfl_xor_sync(0xffffffffu, m0, 2));
        m1 = fmaxf(m1, __shfl_xor_sync(0xffffffffu, m1, 1));
        m1 = fmaxf(m1, __shfl_xor_sync(0xffffffffu, m1, 2));
        const int row0 = tokB2 + g, row1 = row0 + 8;
        if (t == 0) { sRedM[snw * 128 + row0] = m0; sRedM[snw * 128 + row1] = m1; }
        __syncthreads();
        float M0 = fmaxf(m0, sRedM[(1 ^ snw) * 128 + row0]);
        float M1 = fmaxf(m1, sRedM[(1 ^ snw) * 128 + row1]);
        float s0 = 0.0f, s1 = 0.0f;
        #pragma unroll
        for (int i = 0; i < 8; i++) {
            w0[i] = __expf(w0[i] - M0); s0 += w0[i];
            w1[i] = __expf(w1[i] - M1); s1 += w1[i];
        }
        s0 += __shfl_xor_sync(0xffffffffu, s0, 1);
        s0 += __shfl_xor_sync(0xffffffffu, s0, 2);
        s1 += __shfl_xor_sync(0xffffffffu, s1, 1);
        s1 += __shfl_xor_sync(0xffffffffu, s1, 2);
        if (t == 0) { sRedS[snw * 128 + row0] = s0; sRedS[snw * 128 + row1] = s1; }
        __syncthreads();
        float r0inv = __frcp_rn(s0 + sRedS[(1 ^ snw) * 128 + row0]);
        float r1inv = __frcp_rn(s1 + sRedS[(1 ^ snw) * 128 + row1]);

        // ---- w stores (transposed [s][tok]) + norm accumulation ----
        #pragma unroll
        for (int j = 0; j < 4; j++)
            #pragma unroll
            for (int e = 0; e < 2; e++) {
                int s = sB2 + 8 * j + 2 * t + e;
                float v0 = tfF(w0[2 * j + e] * r0inv);
                float v1 = tfF(w1[2 * j + e] * r1inv);
                sWgtT[s * PT + row0] = v0;
                sWgtT[s * PT + row1] = v1;
                na[2 * j + e] += v0 + v1;
            }
        __syncthreads();

        // ---- aggregation: A[s,d] += w^T @ fx, K=128 tokens ----
        #pragma unroll
        for (int ks = 0; ks < 16; ks++) {
            unsigned a0, a1, a2, a3, p0, p1, p2, p3;
            ldsm4(wA0 + ks * 32, a0, a1, a2, a3);
            ldsm4(fB0 + ks * 32, p0, p1, p2, p3);
            mma8(aggAcc[0], a0, a1, a2, a3, p0, p1);
            mma8(aggAcc[1], a0, a1, a2, a3, p2, p3);
        }
    }

    // ---- flush ----
    float* gA = g_A + (size_t)((b * H_ + h) * 64) * 64;
    #pragma unroll
    for (int j = 0; j < 2; j++) {
        int d0 = dB3 + 8 * j + 2 * t;
        atomicAdd(&gA[(sB3 + g) * 64 + d0],         aggAcc[j][0]);
        atomicAdd(&gA[(sB3 + g) * 64 + d0 + 1],     aggAcc[j][1]);
        atomicAdd(&gA[(sB3 + g + 8) * 64 + d0],     aggAcc[j][2]);
        atomicAdd(&gA[(sB3 + g + 8) * 64 + d0 + 1], aggAcc[j][3]);
    }
    #pragma unroll
    for (int i = 0; i < 8; i++) {
        float v = na[i];
        v += __shfl_xor_sync(0xffffffffu, v, 4);
        v += __shfl_xor_sync(0xffffffffu, v, 8);
        v += __shfl_xor_sync(0xffffffffu, v, 16);
        if (lane < 4)
            atomicAdd(&g_norm[(b * H_ + h) * 64 + sB2 + 8 * (i >> 1) + 2 * t + (i & 1)], v);
    }
}

__global__ void k_final(float* __restrict__ out) {
    int i = blockIdx.x * 256 + threadIdx.x;
    out[i] = g_A[i] / (g_norm[i >> 6] + 0.01f);
}

extern "C" void kernel_launch(void* const* d_in, const int* in_sizes, int n_in,
                              void* d_out, int out_size) {
    const float* x    = (const float*)d_in[0];
    const float* Wx   = (const float*)d_in[1];
    const float* bx   = (const float*)d_in[2];
    const float* Wfx  = (const float*)d_in[3];
    const float* bfx  = (const float*)d_in[4];
    const float* Wsl  = (const float*)d_in[5];
    const float* bsl  = (const float*)d_in[6];
    const float* temp = (const float*)d_in[7];
    float* out = (float*)d_out;

    const int smem_bytes = SMEM_FLOATS * 4;   // 224768 B
    cudaFuncSetAttribute(k_fused, cudaFuncAttributeMaxDynamicSharedMemorySize, smem_bytes);

    k_zero<<<256, 256>>>();
    dim3 grid(NCHUNK, H_, B_);
    k_fused<<<grid, 512, smem_bytes>>>(x, Wx, bx, Wfx, bfx, Wsl, bsl, temp);
    k_final<<<256, 256>>>(out);
}